// round 5
// baseline (speedup 1.0000x reference)
#include <cuda_runtime.h>
#include <math.h>

#define B_     64
#define NSIDE  40
#define NPTS   1600
#define S_     512
#define C1_    20
#define W_     128
#define SCN    10240                 // S_*C1_
#define KSPLIT 5                     // k2 n-dim split (320 each)
#define ZPSZ   (SCN * B_)            // one z1 partial plane
#define GSPLIT 16                    // kG s-splits (32 s each)
#define GN     (129 * 1280)          // one G partial plane
#define ZSPLIT 86                    // kZ kc-splits (30 each; 86*30=2580=129*20)

typedef unsigned long long u64;

// ---------------- scratch (device globals; no runtime allocation) ----------------
__device__ __align__(16) float g_filt1[S_ * C1_ * NPTS];   // [sc][n]
__device__ __align__(16) float g_z1p [KSPLIT * ZPSZ];      // [split][sc*64+b]
__device__ __align__(16) float g_h2  [S_ * W_];            // [s][128]
__device__ __align__(16) float g_Gp  [GSPLIT * GN];        // [split][k*1280 + c*64 + b]
__device__ __align__(16) float g_z2p [ZSPLIT * B_ * W_];   // [split][b][w]

// ---------------- f32x2 helpers (Blackwell packed fp32 FMA) -----------------------
__device__ __forceinline__ u64 pk2(float lo, float hi) {
    u64 r; asm("mov.b64 %0, {%1, %2};" : "=l"(r) : "f"(lo), "f"(hi)); return r;
}
__device__ __forceinline__ void upk2(u64 v, float& lo, float& hi) {
    asm("mov.b64 {%0, %1}, %2;" : "=f"(lo), "=f"(hi) : "l"(v));
}
__device__ __forceinline__ void fma2p(u64& d, u64 a, u64 b) {
    asm("fma.rn.f32x2 %0, %1, %2, %0;" : "+l"(d) : "l"(a), "l"(b));
}

__device__ __forceinline__ float silu_f(float x) { return x / (1.0f + __expf(-x)); }
__device__ __forceinline__ float silu_t(float x) {
    float t; asm("tanh.approx.f32 %0, %1;" : "=f"(t) : "f"(0.5f * x));
    return 0.5f * x * (1.0f + t);
}

// ---------------- K1: filt1[sc][n] = MLP(embed(projective coords)) ----------------
#define BP 264   // buf row stride [feat][point]

__device__ __forceinline__ void k1_layer(const float* in, float* out,
                                         const float* w, const float* bias,
                                         int og, int pl)
{
    int ob = og * 10;
    u64 acc[4][5];
#pragma unroll
    for (int ip = 0; ip < 4; ip++)
#pragma unroll
        for (int j = 0; j < 5; j++) acc[ip][j] = pk2(bias[ob + 2*j], bias[ob + 2*j + 1]);
#pragma unroll 4
    for (int i = 0; i < 20; i++) {
        u64 wv[5];
#pragma unroll
        for (int j = 0; j < 5; j++)
            wv[j] = *(const u64*)&w[i * 20 + ob + 2 * j];
#pragma unroll
        for (int ip = 0; ip < 4; ip++) {
            float e = in[i * BP + pl + 64 * ip];
            u64 ed = pk2(e, e);
#pragma unroll
            for (int j = 0; j < 5; j++) fma2p(acc[ip][j], ed, wv[j]);
        }
    }
#pragma unroll
    for (int ip = 0; ip < 4; ip++)
#pragma unroll
        for (int j = 0; j < 5; j++) {
            float a0, a1; upk2(acc[ip][j], a0, a1);
            out[(ob + 2*j)     * BP + pl + 64 * ip] = silu_t(a0);
            out[(ob + 2*j + 1) * BP + pl + 64 * ip] = silu_t(a1);
        }
}

__global__ __launch_bounds__(128) void k1_filt1(
    const float* __restrict__ v_last,
    const float* __restrict__ fw1, const float* __restrict__ fb1,
    const float* __restrict__ fw2, const float* __restrict__ fb2,
    const float* __restrict__ fw3, const float* __restrict__ fb3)
{
    __shared__ __align__(16) float sw1[400], sw2[400], sw3[400];
    __shared__ float sb1[20], sb2[20], sb3[20];
    __shared__ __align__(16) float bufA[20 * BP], bufB[20 * BP];

    int s   = blockIdx.y;
    int n0  = blockIdx.x * 256;
    int tid = threadIdx.x;

    for (int i = tid; i < 400; i += 128) { sw1[i] = fw1[i]; sw2[i] = fw2[i]; sw3[i] = fw3[i]; }
    if (tid < 20) { sb1[tid] = fb1[tid]; sb2[tid] = fb2[tid]; sb3[tid] = fb3[tid]; }

    float v[8];
#pragma unroll
    for (int i = 0; i < 8; i++) v[i] = 0.1f * __ldg(&v_last[s * 8 + i]);

#pragma unroll
    for (int q = 0; q < 2; q++) {
        int p = tid + q * 128;
        int n = n0 + p;
        int ic = n / NSIDE, jc = n - ic * NSIDE;
        float x = -1.0f + (2.0f / 39.0f) * (float)ic;
        float y = -1.0f + (2.0f / 39.0f) * (float)jc;
        float y0 = (1.0f + v[0]) * x + v[1] * y + v[2];
        float y1 = v[3] * x + (1.0f + v[4]) * y + v[5];
        float y2 = v[6] * x + v[7] * y + 1.0f;
        float inv = __frcp_rn(y2);
        float t0 = y0 * inv, t1 = y1 * inv;

        float sa, ca; __sincosf(t0, &sa, &ca);
        bufA[0 * BP + p] = sa; bufA[5 * BP + p] = ca;
#pragma unroll
        for (int k = 1; k < 5; k++) {
            float s2 = 2.0f * sa * ca;
            float c2 = 2.0f * ca * ca - 1.0f;
            bufA[k * BP + p] = s2; bufA[(5 + k) * BP + p] = c2;
            sa = s2; ca = c2;
        }
        __sincosf(t1, &sa, &ca);
        bufA[10 * BP + p] = sa; bufA[15 * BP + p] = ca;
#pragma unroll
        for (int k = 1; k < 5; k++) {
            float s2 = 2.0f * sa * ca;
            float c2 = 2.0f * ca * ca - 1.0f;
            bufA[(10 + k) * BP + p] = s2; bufA[(15 + k) * BP + p] = c2;
            sa = s2; ca = c2;
        }
    }
    __syncthreads();

    int og = tid >> 6;
    int pl = tid & 63;

    k1_layer(bufA, bufB, sw1, sb1, og, pl);
    __syncthreads();
    k1_layer(bufB, bufA, sw2, sb2, og, pl);
    __syncthreads();

    {
        int ob = og * 10;
        u64 acc[4][5];
#pragma unroll
        for (int ip = 0; ip < 4; ip++)
#pragma unroll
            for (int j = 0; j < 5; j++) acc[ip][j] = pk2(sb3[ob + 2*j], sb3[ob + 2*j + 1]);
#pragma unroll 4
        for (int i = 0; i < 20; i++) {
            u64 wv[5];
#pragma unroll
            for (int j = 0; j < 5; j++) wv[j] = *(const u64*)&sw3[i * 20 + ob + 2 * j];
#pragma unroll
            for (int ip = 0; ip < 4; ip++) {
                float e = bufA[i * BP + pl + 64 * ip];
                u64 ed = pk2(e, e);
#pragma unroll
                for (int j = 0; j < 5; j++) fma2p(acc[ip][j], ed, wv[j]);
            }
        }
#pragma unroll
        for (int ip = 0; ip < 4; ip++) {
            int n = n0 + pl + 64 * ip;
            if (n < NPTS) {
#pragma unroll
                for (int j = 0; j < 5; j++) {
                    float a0, a1; upk2(acc[ip][j], a0, a1);
                    g_filt1[(s * C1_ + ob + 2*j)     * NPTS + n] = a0;
                    g_filt1[(s * C1_ + ob + 2*j + 1) * NPTS + n] = a1;
                }
            }
        }
    }
}

// ---------------- K2: z1p[split][sc*64+b] over 320-wide n-range -------------------
// 128 threads, sc-tile 128, k-chunk 32. Pre-duplicated filt pairs in smem:
// inner loop = 4 LDS.128 + 4 LDS.64 + 32 FFMA2 per k (zero dup-MOVs, LSU-balanced).
__global__ __launch_bounds__(128) void k2_z1(const float* __restrict__ data)
{
    __shared__ __align__(16) u64  ftd[32 * 128];   // [k][sc] (f,f) pairs, 32 KB
    __shared__ __align__(16) float dt[32 * 64];    // [k][b], 8 KB

    int sc0   = blockIdx.x * 128;
    int split = blockIdx.y;
    int tid   = threadIdx.x;
    int tc    = tid & 7;     // b = 2*tc + 16*jp
    int sr    = tid >> 3;    // sc = 2*sr + 32*iq (+rr)

    u64 acc[4][2][4];
#pragma unroll
    for (int iq = 0; iq < 4; iq++)
#pragma unroll
        for (int r = 0; r < 2; r++)
#pragma unroll
            for (int jp = 0; jp < 4; jp++) acc[iq][r][jp] = 0ull;

    for (int ch = 0; ch < 10; ch++) {
        int base = split * 320 + ch * 32;
        __syncthreads();
        // filt tile: each thread owns one sc row; dup-pack on store
        {
            const float* src = &g_filt1[(sc0 + tid) * NPTS + base];
#pragma unroll
            for (int q = 0; q < 8; q++) {
                float4 f4 = *(const float4*)&src[4 * q];
                ftd[(4 * q + 0) * 128 + tid] = pk2(f4.x, f4.x);
                ftd[(4 * q + 1) * 128 + tid] = pk2(f4.y, f4.y);
                ftd[(4 * q + 2) * 128 + tid] = pk2(f4.z, f4.z);
                ftd[(4 * q + 3) * 128 + tid] = pk2(f4.w, f4.w);
            }
        }
        // data tile [k][b]
#pragma unroll
        for (int q = 0; q < 16; q++) {
            int i = tid + 128 * q;
            int b = i & 63, k = i >> 6;
            dt[k * 64 + b] = data[b * NPTS + base + k];
        }
        __syncthreads();

#pragma unroll 2
        for (int k = 0; k < 32; k++) {
            u64 fd[4][2];
#pragma unroll
            for (int iq = 0; iq < 4; iq++) {
                ulonglong2 v = *(const ulonglong2*)&ftd[k * 128 + 2 * sr + 32 * iq];
                fd[iq][0] = v.x; fd[iq][1] = v.y;
            }
            u64 dd[4];
#pragma unroll
            for (int jp = 0; jp < 4; jp++)
                dd[jp] = *(const u64*)&dt[k * 64 + 2 * tc + 16 * jp];
#pragma unroll
            for (int iq = 0; iq < 4; iq++)
#pragma unroll
                for (int r = 0; r < 2; r++)
#pragma unroll
                    for (int jp = 0; jp < 4; jp++)
                        fma2p(acc[iq][r][jp], fd[iq][r], dd[jp]);
        }
    }

#pragma unroll
    for (int iq = 0; iq < 4; iq++)
#pragma unroll
        for (int r = 0; r < 2; r++) {
            int sc = sc0 + 2 * sr + r + 32 * iq;
#pragma unroll
            for (int jp = 0; jp < 4; jp++)
                *(u64*)&g_z1p[split * ZPSZ + sc * B_ + 2 * tc + 16 * jp] = acc[iq][r][jp];
        }
}

// ---------------- K3a: h2[s,:] = silu(embed(v0[s]) @ s_w1 + s_b1) -----------------
__global__ __launch_bounds__(128) void k3a_h2(const float* __restrict__ v0,
                                              const float* __restrict__ s_w1,
                                              const float* __restrict__ s_b1)
{
    __shared__ float e[80];
    int s = blockIdx.x, tid = threadIdx.x;
    if (tid < 80) {
        int d = tid / 10, kk = tid % 10;
        float v = v0[s * 8 + d];
        float f = (float)(1 << (kk % 5));
        e[tid] = (kk < 5) ? __sinf(v * f) : __cosf(v * f);
    }
    __syncthreads();
    float a = s_b1[tid];
#pragma unroll 8
    for (int k = 0; k < 80; k++) a += e[k] * s_w1[k * W_ + tid];
    g_h2[s * W_ + tid] = silu_f(a);
}

// ---------------- KG: G[k,cb] partials = sum over 32 s of h2e[s,k] * z1[s,cb] -----
// grid (16 cb-blocks x 16 s-splits), 256 threads. Vectorized (float4) loads.
__global__ __launch_bounds__(256) void kG_contract()
{
    __shared__ float h2s[32 * 129];   // [sl][k], k==128 -> 1 (bias column)
    __shared__ float z1s[32 * 81];    // [sl][cbl]
    int cb0 = blockIdx.x * 80;
    int sp  = blockIdx.y;
    int s0  = sp * 32;
    int tid = threadIdx.x;

    for (int i = tid; i < 32 * 32; i += 256) {       // h2: 32 rows x 32 float4
        int r = i >> 5, k4 = i & 31;
        float4 v = *(const float4*)&g_h2[(s0 + r) * W_ + 4 * k4];
        h2s[r * 129 + 4 * k4 + 0] = v.x; h2s[r * 129 + 4 * k4 + 1] = v.y;
        h2s[r * 129 + 4 * k4 + 2] = v.z; h2s[r * 129 + 4 * k4 + 3] = v.w;
    }
    if (tid < 32) h2s[tid * 129 + 128] = 1.0f;

    for (int i = tid; i < 32 * 20; i += 256) {       // z1p reduce: 32 rows x 20 float4
        int r = i / 20, c4 = i - r * 20;
        int idx = (s0 + r) * 1280 + cb0 + 4 * c4;
        float4 a = *(const float4*)&g_z1p[idx];
#pragma unroll
        for (int p = 1; p < KSPLIT; p++) {
            float4 b = *(const float4*)&g_z1p[p * ZPSZ + idx];
            a.x += b.x; a.y += b.y; a.z += b.z; a.w += b.w;
        }
        float* zr = &z1s[r * 81 + 4 * c4];
        zr[0] = silu_f(a.x * (1.0f / (float)NPTS));
        zr[1] = silu_f(a.y * (1.0f / (float)NPTS));
        zr[2] = silu_f(a.z * (1.0f / (float)NPTS));
        zr[3] = silu_f(a.w * (1.0f / (float)NPTS));
    }
    __syncthreads();

    int kq  = tid & 15;   // k = kq + 16*j (j<8), plus k=128 when kq==0
    int cbq = tid >> 4;   // cb = cbq + 16*i (i<5)

    float acc[9][5];
#pragma unroll
    for (int j = 0; j < 9; j++)
#pragma unroll
        for (int i = 0; i < 5; i++) acc[j][i] = 0.0f;

    for (int sl = 0; sl < 32; sl++) {
        float h[9];
#pragma unroll
        for (int j = 0; j < 8; j++) h[j] = h2s[sl * 129 + kq + 16 * j];
        h[8] = h2s[sl * 129 + 128];
        float z[5];
#pragma unroll
        for (int i = 0; i < 5; i++) z[i] = z1s[sl * 81 + cbq + 16 * i];
#pragma unroll
        for (int j = 0; j < 9; j++)
#pragma unroll
            for (int i = 0; i < 5; i++) acc[j][i] += h[j] * z[i];
    }

#pragma unroll
    for (int j = 0; j < 9; j++) {
        int k = kq + 16 * j;
        if (j < 8 || kq == 0) {
#pragma unroll
            for (int i = 0; i < 5; i++)
                g_Gp[sp * GN + k * 1280 + cb0 + cbq + 16 * i] = acc[j][i];
        }
    }
}

// ---------------- KZ: z2p[split][b][w] = sum over 30 kc of G[k,cb] * W2ext --------
// grid 86 blocks (30 kc each), 256 threads, float4 loads, 4b x 8w / thread
__global__ __launch_bounds__(256) void kZ_out(const float* __restrict__ s_w2,
                                              const float* __restrict__ s_b2)
{
    __shared__ float Gt[30 * 64];    // [kcl][b]
    __shared__ float Wt[30 * 128];   // [kcl][w]
    int kc0 = blockIdx.x * 30;
    int tid = threadIdx.x;

    for (int i = tid; i < 30 * 32; i += 256) {       // W: 30 rows x 32 float4
        int kcl = i >> 5, w4 = i & 31;
        int kc = kc0 + kcl, k = kc / 20, c = kc - k * 20;
        float4 v = (k < 128) ? *(const float4*)&s_w2[k * 2560 + c * 128 + 4 * w4]
                             : *(const float4*)&s_b2[c * 128 + 4 * w4];
        *(float4*)&Wt[kcl * 128 + 4 * w4] = v;
    }
    for (int i = tid; i < 30 * 16; i += 256) {       // G reduce: 30 rows x 16 float4
        int kcl = i >> 4, b4 = i & 15;
        int kc = kc0 + kcl, k = kc / 20, c = kc - k * 20;
        int gi = k * 1280 + c * 64 + 4 * b4;
        float4 a = *(const float4*)&g_Gp[gi];
#pragma unroll
        for (int p = 1; p < GSPLIT; p++) {
            float4 b = *(const float4*)&g_Gp[p * GN + gi];
            a.x += b.x; a.y += b.y; a.z += b.z; a.w += b.w;
        }
        *(float4*)&Gt[kcl * 64 + 4 * b4] = a;
    }
    __syncthreads();

    int wq = tid & 15;   // w = wq + 16*m
    int bq = tid >> 4;   // b = bq + 16*i
    float acc[4][8];
#pragma unroll
    for (int i = 0; i < 4; i++)
#pragma unroll
        for (int m = 0; m < 8; m++) acc[i][m] = 0.0f;

    for (int kcl = 0; kcl < 30; kcl++) {
        float g[4];
#pragma unroll
        for (int i = 0; i < 4; i++) g[i] = Gt[kcl * 64 + bq + 16 * i];
#pragma unroll
        for (int m = 0; m < 8; m++) {
            float w = Wt[kcl * 128 + wq + 16 * m];
#pragma unroll
            for (int i = 0; i < 4; i++) acc[i][m] += g[i] * w;
        }
    }
#pragma unroll
    for (int i = 0; i < 4; i++)
#pragma unroll
        for (int m = 0; m < 8; m++)
            g_z2p[blockIdx.x * (B_ * W_) + (bq + 16 * i) * W_ + wq + 16 * m] = acc[i][m];
}

// ---------------- K5: reduce partials, residual MLP, pool -------------------------
__global__ __launch_bounds__(128) void k5_head(const float* __restrict__ fc1_w,
                                               const float* __restrict__ fc1_b,
                                               const float* __restrict__ fc2_w,
                                               const float* __restrict__ fc2_b,
                                               const float* __restrict__ pool_w,
                                               const float* __restrict__ pool_b,
                                               float* __restrict__ out)
{
    __shared__ float zs[128], r1[128], r2[128];
    int b = blockIdx.x, w = threadIdx.x;

    float a = 0.0f;
#pragma unroll 8
    for (int p = 0; p < ZSPLIT; p++) a += g_z2p[p * (B_ * W_) + b * W_ + w];
    a *= (1.0f / (float)S_);
    zs[w] = a;
    __syncthreads();

    float u = fc1_b[w];
#pragma unroll 8
    for (int k = 0; k < 128; k++) u += zs[k] * fc1_w[k * W_ + w];
    r1[w] = silu_f(u) + zs[w];
    __syncthreads();

    u = fc2_b[w];
#pragma unroll 8
    for (int k = 0; k < 128; k++) u += r1[k] * fc2_w[k * W_ + w];
    r2[w] = silu_f(u) + r1[w];
    __syncthreads();

    if (w < 10) {
        float o = pool_b[w];
        for (int k = 0; k < 128; k++) o += r2[k] * pool_w[k * 10 + w];
        out[b * 10 + w] = o;
    }
}

// ---------------- host launcher ---------------------------------------------------
extern "C" void kernel_launch(void* const* d_in, const int* in_sizes, int n_in,
                              void* d_out, int out_size)
{
    const float* data   = (const float*)d_in[0];
    const float* v0     = (const float*)d_in[1];
    const float* v_last = (const float*)d_in[2];
    const float* fl_w1  = (const float*)d_in[3];
    const float* fl_b1  = (const float*)d_in[4];
    const float* fl_w2  = (const float*)d_in[5];
    const float* fl_b2  = (const float*)d_in[6];
    const float* fl_w3  = (const float*)d_in[7];
    const float* fl_b3  = (const float*)d_in[8];
    const float* s_w1   = (const float*)d_in[9];
    const float* s_b1   = (const float*)d_in[10];
    const float* s_w2   = (const float*)d_in[11];
    const float* s_b2   = (const float*)d_in[12];
    const float* fc1_w  = (const float*)d_in[13];
    const float* fc1_b  = (const float*)d_in[14];
    const float* fc2_w  = (const float*)d_in[15];
    const float* fc2_b  = (const float*)d_in[16];
    const float* pool_w = (const float*)d_in[17];
    const float* pool_b = (const float*)d_in[18];

    k1_filt1<<<dim3(7, S_), 128>>>(v_last, fl_w1, fl_b1, fl_w2, fl_b2, fl_w3, fl_b3);
    k2_z1<<<dim3(80, KSPLIT), 128>>>(data);
    k3a_h2<<<S_, 128>>>(v0, s_w1, s_b1);
    kG_contract<<<dim3(16, GSPLIT), 256>>>();
    kZ_out<<<ZSPLIT, 256>>>(s_w2, s_b2);
    k5_head<<<B_, 128>>>(fc1_w, fc1_b, fc2_w, fc2_b, pool_w, pool_b, (float*)d_out);
}

// round 6
// speedup vs baseline: 1.0497x; 1.0497x over previous
#include <cuda_runtime.h>
#include <math.h>

#define B_     64
#define NSIDE  40
#define NPTS   1600
#define S_     512
#define C1_    20
#define W_     128
#define SCN    10240                 // S_*C1_
#define KSPLIT 5                     // k2 n-dim split (320 each)
#define GSPLIT 16                    // kG s-splits (32 s each)
#define ZSPLIT 86                    // kZ kc-splits (30 each; 86*30=2580=129*20)

typedef unsigned long long u64;

// ---------------- scratch (device globals; no runtime allocation) ----------------
__device__ __align__(16) float g_filt1[S_ * C1_ * NPTS];   // [sc][n]
__device__ __align__(16) float g_z1  [SCN * B_];           // atomic accum [sc][b]
__device__ __align__(16) float g_h2  [S_ * W_];            // [s][128]
__device__ __align__(16) float g_G   [129 * 1280];         // atomic accum [k][c*64+b]
__device__ __align__(16) float g_z2  [B_ * W_];            // atomic accum [b][w]

// ---------------- f32x2 helpers (Blackwell packed fp32 FMA) -----------------------
__device__ __forceinline__ u64 pk2(float lo, float hi) {
    u64 r; asm("mov.b64 %0, {%1, %2};" : "=l"(r) : "f"(lo), "f"(hi)); return r;
}
__device__ __forceinline__ void upk2(u64 v, float& lo, float& hi) {
    asm("mov.b64 {%0, %1}, %2;" : "=f"(lo), "=f"(hi) : "l"(v));
}
__device__ __forceinline__ void fma2p(u64& d, u64 a, u64 b) {
    asm("fma.rn.f32x2 %0, %1, %2, %0;" : "+l"(d) : "l"(a), "l"(b));
}

__device__ __forceinline__ float silu_f(float x) { return x / (1.0f + __expf(-x)); }
__device__ __forceinline__ float silu_t(float x) {
    float t; asm("tanh.approx.f32 %0, %1;" : "=f"(t) : "f"(0.5f * x));
    return 0.5f * x * (1.0f + t);
}

// ---------------- K0: zero the atomic accumulators (per replay) -------------------
__global__ __launch_bounds__(256) void kzero()
{
    int i = blockIdx.x * 256 + threadIdx.x;
    float4 z = make_float4(0.f, 0.f, 0.f, 0.f);
    ((float4*)g_z1)[i] = z;                        // 163840 float4
    if (i < 129 * 1280 / 4) ((float4*)g_G)[i] = z; // 41280
    if (i < B_ * W_ / 4)    ((float4*)g_z2)[i] = z;
}

// ---------------- K1: filt1[sc][n] = MLP(embed(projective coords)) ----------------
#define BP 264   // buf row stride [feat][point]

__device__ __forceinline__ void k1_layer(const float* in, float* out,
                                         const float* w, const float* bias,
                                         int og, int pl)
{
    int ob = og * 10;
    u64 acc[4][5];
#pragma unroll
    for (int ip = 0; ip < 4; ip++)
#pragma unroll
        for (int j = 0; j < 5; j++) acc[ip][j] = pk2(bias[ob + 2*j], bias[ob + 2*j + 1]);
#pragma unroll 4
    for (int i = 0; i < 20; i++) {
        u64 wv[5];
#pragma unroll
        for (int j = 0; j < 5; j++)
            wv[j] = *(const u64*)&w[i * 20 + ob + 2 * j];
#pragma unroll
        for (int ip = 0; ip < 4; ip++) {
            float e = in[i * BP + pl + 64 * ip];
            u64 ed = pk2(e, e);
#pragma unroll
            for (int j = 0; j < 5; j++) fma2p(acc[ip][j], ed, wv[j]);
        }
    }
#pragma unroll
    for (int ip = 0; ip < 4; ip++)
#pragma unroll
        for (int j = 0; j < 5; j++) {
            float a0, a1; upk2(acc[ip][j], a0, a1);
            out[(ob + 2*j)     * BP + pl + 64 * ip] = silu_t(a0);
            out[(ob + 2*j + 1) * BP + pl + 64 * ip] = silu_t(a1);
        }
}

__global__ __launch_bounds__(128) void k1_filt1(
    const float* __restrict__ v_last,
    const float* __restrict__ fw1, const float* __restrict__ fb1,
    const float* __restrict__ fw2, const float* __restrict__ fb2,
    const float* __restrict__ fw3, const float* __restrict__ fb3)
{
    __shared__ __align__(16) float sw1[400], sw2[400], sw3[400];
    __shared__ float sb1[20], sb2[20], sb3[20];
    __shared__ __align__(16) float bufA[20 * BP], bufB[20 * BP];

    int s   = blockIdx.y;
    int n0  = blockIdx.x * 256;
    int tid = threadIdx.x;

    for (int i = tid; i < 400; i += 128) { sw1[i] = fw1[i]; sw2[i] = fw2[i]; sw3[i] = fw3[i]; }
    if (tid < 20) { sb1[tid] = fb1[tid]; sb2[tid] = fb2[tid]; sb3[tid] = fb3[tid]; }

    float v[8];
#pragma unroll
    for (int i = 0; i < 8; i++) v[i] = 0.1f * __ldg(&v_last[s * 8 + i]);

#pragma unroll
    for (int q = 0; q < 2; q++) {
        int p = tid + q * 128;
        int n = n0 + p;
        int ic = n / NSIDE, jc = n - ic * NSIDE;
        float x = -1.0f + (2.0f / 39.0f) * (float)ic;
        float y = -1.0f + (2.0f / 39.0f) * (float)jc;
        float y0 = (1.0f + v[0]) * x + v[1] * y + v[2];
        float y1 = v[3] * x + (1.0f + v[4]) * y + v[5];
        float y2 = v[6] * x + v[7] * y + 1.0f;
        float inv = __frcp_rn(y2);
        float t0 = y0 * inv, t1 = y1 * inv;

        float sa, ca; __sincosf(t0, &sa, &ca);
        bufA[0 * BP + p] = sa; bufA[5 * BP + p] = ca;
#pragma unroll
        for (int k = 1; k < 5; k++) {
            float s2 = 2.0f * sa * ca;
            float c2 = 2.0f * ca * ca - 1.0f;
            bufA[k * BP + p] = s2; bufA[(5 + k) * BP + p] = c2;
            sa = s2; ca = c2;
        }
        __sincosf(t1, &sa, &ca);
        bufA[10 * BP + p] = sa; bufA[15 * BP + p] = ca;
#pragma unroll
        for (int k = 1; k < 5; k++) {
            float s2 = 2.0f * sa * ca;
            float c2 = 2.0f * ca * ca - 1.0f;
            bufA[(10 + k) * BP + p] = s2; bufA[(15 + k) * BP + p] = c2;
            sa = s2; ca = c2;
        }
    }
    __syncthreads();

    int og = tid >> 6;
    int pl = tid & 63;

    k1_layer(bufA, bufB, sw1, sb1, og, pl);
    __syncthreads();
    k1_layer(bufB, bufA, sw2, sb2, og, pl);
    __syncthreads();

    {
        int ob = og * 10;
        u64 acc[4][5];
#pragma unroll
        for (int ip = 0; ip < 4; ip++)
#pragma unroll
            for (int j = 0; j < 5; j++) acc[ip][j] = pk2(sb3[ob + 2*j], sb3[ob + 2*j + 1]);
#pragma unroll 4
        for (int i = 0; i < 20; i++) {
            u64 wv[5];
#pragma unroll
            for (int j = 0; j < 5; j++) wv[j] = *(const u64*)&sw3[i * 20 + ob + 2 * j];
#pragma unroll
            for (int ip = 0; ip < 4; ip++) {
                float e = bufA[i * BP + pl + 64 * ip];
                u64 ed = pk2(e, e);
#pragma unroll
                for (int j = 0; j < 5; j++) fma2p(acc[ip][j], ed, wv[j]);
            }
        }
#pragma unroll
        for (int ip = 0; ip < 4; ip++) {
            int n = n0 + pl + 64 * ip;
            if (n < NPTS) {
#pragma unroll
                for (int j = 0; j < 5; j++) {
                    float a0, a1; upk2(acc[ip][j], a0, a1);
                    g_filt1[(s * C1_ + ob + 2*j)     * NPTS + n] = a0;
                    g_filt1[(s * C1_ + ob + 2*j + 1) * NPTS + n] = a1;
                }
            }
        }
    }
}

// ---------------- K2: g_z1[sc][b] += filt1 . data over 320-wide n-range -----------
// 128 threads, sc-tile 128, k-chunk 40. Coalesced tile loads; dup-packed (f,f)
// pairs stored once; inner loop = 12 LDS-wf vs 64 FFMA2-SMSP-cyc -> FMA-bound.
__global__ __launch_bounds__(128) void k2_z1(const float* __restrict__ data)
{
    __shared__ __align__(16) u64  ftd[128 * 42];   // [sc][k], stride 42 (bank-clean)
    __shared__ __align__(16) float dt[40 * 66];    // [k][b]

    int sc0   = blockIdx.x * 128;
    int split = blockIdx.y;
    int tid   = threadIdx.x;
    int tc    = tid & 7;     // b = 2*tc + 16*jp
    int sr    = tid >> 3;    // sc = sr + 16*iq

    u64 acc[8][4];
#pragma unroll
    for (int iq = 0; iq < 8; iq++)
#pragma unroll
        for (int jp = 0; jp < 4; jp++) acc[iq][jp] = 0ull;

    for (int ch = 0; ch < 8; ch++) {
        int base = split * 320 + ch * 40;
        __syncthreads();
        // filt tile: coalesced 40-float runs, dup-pack on store
        for (int i = tid; i < 128 * 40; i += 128) {
            int r = i / 40, k = i - r * 40;
            float f = g_filt1[(sc0 + r) * NPTS + base + k];
            ftd[r * 42 + k] = pk2(f, f);
        }
        // data tile [k][b]: coalesced 40-float runs
        for (int i = tid; i < 64 * 40; i += 128) {
            int b = i / 40, k = i - b * 40;
            dt[k * 66 + b] = data[b * NPTS + base + k];
        }
        __syncthreads();

#pragma unroll 2
        for (int k = 0; k < 40; k++) {
            u64 fd[8];
#pragma unroll
            for (int iq = 0; iq < 8; iq++) fd[iq] = ftd[(sr + 16 * iq) * 42 + k];
            u64 dd[4];
#pragma unroll
            for (int jp = 0; jp < 4; jp++)
                dd[jp] = *(const u64*)&dt[k * 66 + 2 * tc + 16 * jp];
#pragma unroll
            for (int iq = 0; iq < 8; iq++)
#pragma unroll
                for (int jp = 0; jp < 4; jp++) fma2p(acc[iq][jp], fd[iq], dd[jp]);
        }
    }

#pragma unroll
    for (int iq = 0; iq < 8; iq++) {
        int sc = sc0 + sr + 16 * iq;
#pragma unroll
        for (int jp = 0; jp < 4; jp++) {
            float a0, a1; upk2(acc[iq][jp], a0, a1);
            atomicAdd(&g_z1[sc * B_ + 2 * tc + 16 * jp],     a0);
            atomicAdd(&g_z1[sc * B_ + 2 * tc + 16 * jp + 1], a1);
        }
    }
}

// ---------------- K3a: h2[s,:] = silu(embed(v0[s]) @ s_w1 + s_b1) -----------------
__global__ __launch_bounds__(128) void k3a_h2(const float* __restrict__ v0,
                                              const float* __restrict__ s_w1,
                                              const float* __restrict__ s_b1)
{
    __shared__ float e[80];
    int s = blockIdx.x, tid = threadIdx.x;
    if (tid < 80) {
        int d = tid / 10, kk = tid % 10;
        float v = v0[s * 8 + d];
        float f = (float)(1 << (kk % 5));
        e[tid] = (kk < 5) ? __sinf(v * f) : __cosf(v * f);
    }
    __syncthreads();
    float a = s_b1[tid];
#pragma unroll 8
    for (int k = 0; k < 80; k++) a += e[k] * s_w1[k * W_ + tid];
    g_h2[s * W_ + tid] = silu_f(a);
}

// ---------------- KG: g_G[k,cb] += sum over 32 s of h2e[s,k] * silu(z1/N)[s,cb] ---
// grid (16 cb-blocks x 16 s-splits), 256 threads, float4 loads, atomic out.
__global__ __launch_bounds__(256) void kG_contract()
{
    __shared__ float h2s[32 * 129];   // [sl][k], k==128 -> 1 (bias column)
    __shared__ float z1s[32 * 81];    // [sl][cbl]
    int cb0 = blockIdx.x * 80;
    int s0  = blockIdx.y * 32;
    int tid = threadIdx.x;

    for (int i = tid; i < 32 * 32; i += 256) {
        int r = i >> 5, k4 = i & 31;
        float4 v = *(const float4*)&g_h2[(s0 + r) * W_ + 4 * k4];
        h2s[r * 129 + 4 * k4 + 0] = v.x; h2s[r * 129 + 4 * k4 + 1] = v.y;
        h2s[r * 129 + 4 * k4 + 2] = v.z; h2s[r * 129 + 4 * k4 + 3] = v.w;
    }
    if (tid < 32) h2s[tid * 129 + 128] = 1.0f;

    for (int i = tid; i < 32 * 20; i += 256) {
        int r = i / 20, c4 = i - r * 20;
        float4 a = *(const float4*)&g_z1[(s0 + r) * 1280 + cb0 + 4 * c4];
        float* zr = &z1s[r * 81 + 4 * c4];
        zr[0] = silu_f(a.x * (1.0f / (float)NPTS));
        zr[1] = silu_f(a.y * (1.0f / (float)NPTS));
        zr[2] = silu_f(a.z * (1.0f / (float)NPTS));
        zr[3] = silu_f(a.w * (1.0f / (float)NPTS));
    }
    __syncthreads();

    int kq  = tid & 15;   // k = kq + 16*j (j<8), plus k=128 when kq==0
    int cbq = tid >> 4;   // cb = cbq + 16*i (i<5)

    float acc[9][5];
#pragma unroll
    for (int j = 0; j < 9; j++)
#pragma unroll
        for (int i = 0; i < 5; i++) acc[j][i] = 0.0f;

    for (int sl = 0; sl < 32; sl++) {
        float h[9];
#pragma unroll
        for (int j = 0; j < 8; j++) h[j] = h2s[sl * 129 + kq + 16 * j];
        h[8] = h2s[sl * 129 + 128];
        float z[5];
#pragma unroll
        for (int i = 0; i < 5; i++) z[i] = z1s[sl * 81 + cbq + 16 * i];
#pragma unroll
        for (int j = 0; j < 9; j++)
#pragma unroll
            for (int i = 0; i < 5; i++) acc[j][i] += h[j] * z[i];
    }

#pragma unroll
    for (int j = 0; j < 9; j++) {
        int k = kq + 16 * j;
        if (j < 8 || kq == 0) {
#pragma unroll
            for (int i = 0; i < 5; i++)
                atomicAdd(&g_G[k * 1280 + cb0 + cbq + 16 * i], acc[j][i]);
        }
    }
}

// ---------------- KZ: g_z2[b][w] += sum over 30 kc of G[k,cb] * W2ext -------------
// grid 86 blocks (30 kc each), 256 threads, float4 loads, atomic out.
__global__ __launch_bounds__(256) void kZ_out(const float* __restrict__ s_w2,
                                              const float* __restrict__ s_b2)
{
    __shared__ float Gt[30 * 64];    // [kcl][b]
    __shared__ float Wt[30 * 128];   // [kcl][w]
    int kc0 = blockIdx.x * 30;
    int tid = threadIdx.x;

    for (int i = tid; i < 30 * 32; i += 256) {
        int kcl = i >> 5, w4 = i & 31;
        int kc = kc0 + kcl, k = kc / 20, c = kc - k * 20;
        float4 v = (k < 128) ? *(const float4*)&s_w2[k * 2560 + c * 128 + 4 * w4]
                             : *(const float4*)&s_b2[c * 128 + 4 * w4];
        *(float4*)&Wt[kcl * 128 + 4 * w4] = v;
    }
    for (int i = tid; i < 30 * 16; i += 256) {
        int kcl = i >> 4, b4 = i & 15;
        int kc = kc0 + kcl, k = kc / 20, c = kc - k * 20;
        float4 a = *(const float4*)&g_G[k * 1280 + c * 64 + 4 * b4];
        *(float4*)&Gt[kcl * 64 + 4 * b4] = a;
    }
    __syncthreads();

    int wq = tid & 15;   // w = wq + 16*m
    int bq = tid >> 4;   // b = bq + 16*i
    float acc[4][8];
#pragma unroll
    for (int i = 0; i < 4; i++)
#pragma unroll
        for (int m = 0; m < 8; m++) acc[i][m] = 0.0f;

    for (int kcl = 0; kcl < 30; kcl++) {
        float g[4];
#pragma unroll
        for (int i = 0; i < 4; i++) g[i] = Gt[kcl * 64 + bq + 16 * i];
#pragma unroll
        for (int m = 0; m < 8; m++) {
            float w = Wt[kcl * 128 + wq + 16 * m];
#pragma unroll
            for (int i = 0; i < 4; i++) acc[i][m] += g[i] * w;
        }
    }
#pragma unroll
    for (int i = 0; i < 4; i++)
#pragma unroll
        for (int m = 0; m < 8; m++)
            atomicAdd(&g_z2[(bq + 16 * i) * W_ + wq + 16 * m], acc[i][m]);
}

// ---------------- K5: residual MLP + pool -----------------------------------------
__global__ __launch_bounds__(128) void k5_head(const float* __restrict__ fc1_w,
                                               const float* __restrict__ fc1_b,
                                               const float* __restrict__ fc2_w,
                                               const float* __restrict__ fc2_b,
                                               const float* __restrict__ pool_w,
                                               const float* __restrict__ pool_b,
                                               float* __restrict__ out)
{
    __shared__ float zs[128], r1[128], r2[128];
    int b = blockIdx.x, w = threadIdx.x;

    float a = g_z2[b * W_ + w] * (1.0f / (float)S_);
    zs[w] = a;
    __syncthreads();

    float u = fc1_b[w];
#pragma unroll 8
    for (int k = 0; k < 128; k++) u += zs[k] * fc1_w[k * W_ + w];
    r1[w] = silu_f(u) + zs[w];
    __syncthreads();

    u = fc2_b[w];
#pragma unroll 8
    for (int k = 0; k < 128; k++) u += r1[k] * fc2_w[k * W_ + w];
    r2[w] = silu_f(u) + r1[w];
    __syncthreads();

    if (w < 10) {
        float o = pool_b[w];
        for (int k = 0; k < 128; k++) o += r2[k] * pool_w[k * 10 + w];
        out[b * 10 + w] = o;
    }
}

// ---------------- host launcher ---------------------------------------------------
extern "C" void kernel_launch(void* const* d_in, const int* in_sizes, int n_in,
                              void* d_out, int out_size)
{
    const float* data   = (const float*)d_in[0];
    const float* v0     = (const float*)d_in[1];
    const float* v_last = (const float*)d_in[2];
    const float* fl_w1  = (const float*)d_in[3];
    const float* fl_b1  = (const float*)d_in[4];
    const float* fl_w2  = (const float*)d_in[5];
    const float* fl_b2  = (const float*)d_in[6];
    const float* fl_w3  = (const float*)d_in[7];
    const float* fl_b3  = (const float*)d_in[8];
    const float* s_w1   = (const float*)d_in[9];
    const float* s_b1   = (const float*)d_in[10];
    const float* s_w2   = (const float*)d_in[11];
    const float* s_b2   = (const float*)d_in[12];
    const float* fc1_w  = (const float*)d_in[13];
    const float* fc1_b  = (const float*)d_in[14];
    const float* fc2_w  = (const float*)d_in[15];
    const float* fc2_b  = (const float*)d_in[16];
    const float* pool_w = (const float*)d_in[17];
    const float* pool_b = (const float*)d_in[18];

    kzero<<<640, 256>>>();
    k3a_h2<<<S_, 128>>>(v0, s_w1, s_b1);
    k1_filt1<<<dim3(7, S_), 128>>>(v_last, fl_w1, fl_b1, fl_w2, fl_b2, fl_w3, fl_b3);
    k2_z1<<<dim3(80, KSPLIT), 128>>>(data);
    kG_contract<<<dim3(16, GSPLIT), 256>>>();
    kZ_out<<<ZSPLIT, 256>>>(s_w2, s_b2);
    k5_head<<<B_, 128>>>(fc1_w, fc1_b, fc2_w, fc2_b, pool_w, pool_b, (float*)d_out);
}

// round 7
// speedup vs baseline: 1.1194x; 1.0663x over previous
#include <cuda_runtime.h>
#include <math.h>

#define B_     64
#define NSIDE  40
#define NPTS   1600
#define S_     512
#define C1_    20
#define W_     128
#define SCN    10240                 // S_*C1_
#define KSPLIT 5                     // k2 n-dim split (320 each)
#define GSPLIT 16                    // kG s-splits (32 s each)
#define ZSPLIT 86                    // kZ kc-splits (30 each)
#define KCH    40                    // k2 k-chunk

typedef unsigned long long u64;

// ---------------- scratch (device globals; no runtime allocation) ----------------
__device__ __align__(16) float g_filt1[S_ * C1_ * NPTS];   // [sc][n]
__device__ __align__(16) float g_z1  [SCN * B_];           // atomic accum [sc][b]
__device__ __align__(16) float g_h2  [S_ * W_];            // [s][128]
__device__ __align__(16) float g_G   [129 * 1280];         // atomic accum [k][c*64+b]
__device__ __align__(16) float g_z2  [B_ * W_];            // atomic accum [b][w]

// ---------------- f32x2 helpers (Blackwell packed fp32 FMA) -----------------------
__device__ __forceinline__ u64 pk2(float lo, float hi) {
    u64 r; asm("mov.b64 %0, {%1, %2};" : "=l"(r) : "f"(lo), "f"(hi)); return r;
}
__device__ __forceinline__ void upk2(u64 v, float& lo, float& hi) {
    asm("mov.b64 {%0, %1}, %2;" : "=f"(lo), "=f"(hi) : "l"(v));
}
__device__ __forceinline__ void fma2p(u64& d, u64 a, u64 b) {
    asm("fma.rn.f32x2 %0, %1, %2, %0;" : "+l"(d) : "l"(a), "l"(b));
}

__device__ __forceinline__ float silu_f(float x) { return x / (1.0f + __expf(-x)); }
__device__ __forceinline__ float silu_t(float x) {
    float t; asm("tanh.approx.f32 %0, %1;" : "=f"(t) : "f"(0.5f * x));
    return 0.5f * x * (1.0f + t);
}

// ---------------- K0: zero the atomic accumulators (per replay) -------------------
__global__ __launch_bounds__(256) void kzero()
{
    int i = blockIdx.x * 256 + threadIdx.x;
    float4 z = make_float4(0.f, 0.f, 0.f, 0.f);
    ((float4*)g_z1)[i] = z;                        // 163840 float4
    if (i < 129 * 1280 / 4) ((float4*)g_G)[i] = z;
    if (i < B_ * W_ / 4)    ((float4*)g_z2)[i] = z;
}

// ---------------- K1: filt1[sc][n] = MLP(embed(projective coords)) ----------------
#define BP 264   // buf row stride [feat][point]

__device__ __forceinline__ void k1_layer(const float* in, float* out,
                                         const float* w, const float* bias,
                                         int og, int pl)
{
    int ob = og * 10;
    u64 acc[4][5];
#pragma unroll
    for (int ip = 0; ip < 4; ip++)
#pragma unroll
        for (int j = 0; j < 5; j++) acc[ip][j] = pk2(bias[ob + 2*j], bias[ob + 2*j + 1]);
#pragma unroll 4
    for (int i = 0; i < 20; i++) {
        u64 wv[5];
#pragma unroll
        for (int j = 0; j < 5; j++)
            wv[j] = *(const u64*)&w[i * 20 + ob + 2 * j];
#pragma unroll
        for (int ip = 0; ip < 4; ip++) {
            float e = in[i * BP + pl + 64 * ip];
            u64 ed = pk2(e, e);
#pragma unroll
            for (int j = 0; j < 5; j++) fma2p(acc[ip][j], ed, wv[j]);
        }
    }
#pragma unroll
    for (int ip = 0; ip < 4; ip++)
#pragma unroll
        for (int j = 0; j < 5; j++) {
            float a0, a1; upk2(acc[ip][j], a0, a1);
            out[(ob + 2*j)     * BP + pl + 64 * ip] = silu_t(a0);
            out[(ob + 2*j + 1) * BP + pl + 64 * ip] = silu_t(a1);
        }
}

__global__ __launch_bounds__(128) void k1_filt1(
    const float* __restrict__ v_last,
    const float* __restrict__ fw1, const float* __restrict__ fb1,
    const float* __restrict__ fw2, const float* __restrict__ fb2,
    const float* __restrict__ fw3, const float* __restrict__ fb3)
{
    __shared__ __align__(16) float sw1[400], sw2[400], sw3[400];
    __shared__ float sb1[20], sb2[20], sb3[20];
    __shared__ __align__(16) float bufA[20 * BP], bufB[20 * BP];

    int s   = blockIdx.y;
    int n0  = blockIdx.x * 256;
    int tid = threadIdx.x;

    for (int i = tid; i < 400; i += 128) { sw1[i] = fw1[i]; sw2[i] = fw2[i]; sw3[i] = fw3[i]; }
    if (tid < 20) { sb1[tid] = fb1[tid]; sb2[tid] = fb2[tid]; sb3[tid] = fb3[tid]; }

    float v[8];
#pragma unroll
    for (int i = 0; i < 8; i++) v[i] = 0.1f * __ldg(&v_last[s * 8 + i]);

#pragma unroll
    for (int q = 0; q < 2; q++) {
        int p = tid + q * 128;
        int n = n0 + p;
        int ic = n / NSIDE, jc = n - ic * NSIDE;
        float x = -1.0f + (2.0f / 39.0f) * (float)ic;
        float y = -1.0f + (2.0f / 39.0f) * (float)jc;
        float y0 = (1.0f + v[0]) * x + v[1] * y + v[2];
        float y1 = v[3] * x + (1.0f + v[4]) * y + v[5];
        float y2 = v[6] * x + v[7] * y + 1.0f;
        float inv = __frcp_rn(y2);
        float t0 = y0 * inv, t1 = y1 * inv;

        float sa, ca; __sincosf(t0, &sa, &ca);
        bufA[0 * BP + p] = sa; bufA[5 * BP + p] = ca;
#pragma unroll
        for (int k = 1; k < 5; k++) {
            float s2 = 2.0f * sa * ca;
            float c2 = 2.0f * ca * ca - 1.0f;
            bufA[k * BP + p] = s2; bufA[(5 + k) * BP + p] = c2;
            sa = s2; ca = c2;
        }
        __sincosf(t1, &sa, &ca);
        bufA[10 * BP + p] = sa; bufA[15 * BP + p] = ca;
#pragma unroll
        for (int k = 1; k < 5; k++) {
            float s2 = 2.0f * sa * ca;
            float c2 = 2.0f * ca * ca - 1.0f;
            bufA[(10 + k) * BP + p] = s2; bufA[(15 + k) * BP + p] = c2;
            sa = s2; ca = c2;
        }
    }
    __syncthreads();

    int og = tid >> 6;
    int pl = tid & 63;

    k1_layer(bufA, bufB, sw1, sb1, og, pl);
    __syncthreads();
    k1_layer(bufB, bufA, sw2, sb2, og, pl);
    __syncthreads();

    {
        int ob = og * 10;
        u64 acc[4][5];
#pragma unroll
        for (int ip = 0; ip < 4; ip++)
#pragma unroll
            for (int j = 0; j < 5; j++) acc[ip][j] = pk2(sb3[ob + 2*j], sb3[ob + 2*j + 1]);
#pragma unroll 4
        for (int i = 0; i < 20; i++) {
            u64 wv[5];
#pragma unroll
            for (int j = 0; j < 5; j++) wv[j] = *(const u64*)&sw3[i * 20 + ob + 2 * j];
#pragma unroll
            for (int ip = 0; ip < 4; ip++) {
                float e = bufA[i * BP + pl + 64 * ip];
                u64 ed = pk2(e, e);
#pragma unroll
                for (int j = 0; j < 5; j++) fma2p(acc[ip][j], ed, wv[j]);
            }
        }
#pragma unroll
        for (int ip = 0; ip < 4; ip++) {
            int n = n0 + pl + 64 * ip;
            if (n < NPTS) {
#pragma unroll
                for (int j = 0; j < 5; j++) {
                    float a0, a1; upk2(acc[ip][j], a0, a1);
                    g_filt1[(s * C1_ + ob + 2*j)     * NPTS + n] = a0;
                    g_filt1[(s * C1_ + ob + 2*j + 1) * NPTS + n] = a1;
                }
            }
        }
    }
}

// ---------------- K2: g_z1[sc][b] += filt1 . data over 320-wide n-range -----------
// 256 threads, tile 128sc x 64b, per-thread 8sc x 4b. sc-PAIR packing: f pairs come
// contiguous from k-major plain-float ft (natural LDS.64); data dup-packed (d,d).
// Per k: 8 LDS.64 wf + 16 FFMA2 (32 SMSP-cyc) -> FMA-bound with 4x LSU headroom.
// smem 41.6 KB, 4 blocks/SM -> 32 warps/SM.
__global__ __launch_bounds__(256, 4) void k2_z1(const float* __restrict__ data)
{
    __shared__ __align__(16) float ft[KCH * 130];   // [k][sc], stride 130
    __shared__ __align__(16) u64  dtd[KCH * 65];    // [k][b] dup pairs, stride 65

    int sc0   = blockIdx.x * 128;
    int split = blockIdx.y;
    int tid   = threadIdx.x;
    int bq    = tid & 15;     // b = bq + 16*jb
    int sq    = tid >> 4;     // sc-pair = sq + 16*ip  ->  sc = 2*pair

    u64 acc[4][4];
#pragma unroll
    for (int ip = 0; ip < 4; ip++)
#pragma unroll
        for (int jb = 0; jb < 4; jb++) acc[ip][jb] = 0ull;

    for (int ch = 0; ch < 8; ch++) {
        int base = split * 320 + ch * KCH;
        __syncthreads();
        for (int i = tid; i < 128 * KCH; i += 256) {        // 20 iters, coalesced 40-runs
            int r = i / KCH, k = i - r * KCH;
            ft[k * 130 + r] = g_filt1[(sc0 + r) * NPTS + base + k];
        }
        for (int i = tid; i < 64 * KCH; i += 256) {         // 10 iters
            int b = i / KCH, k = i - b * KCH;
            float d = data[b * NPTS + base + k];
            dtd[k * 65 + b] = pk2(d, d);
        }
        __syncthreads();

#pragma unroll 2
        for (int k = 0; k < KCH; k++) {
            u64 fd[4];
#pragma unroll
            for (int ip = 0; ip < 4; ip++)
                fd[ip] = *(const u64*)&ft[k * 130 + 2 * (sq + 16 * ip)];
            u64 dd[4];
#pragma unroll
            for (int jb = 0; jb < 4; jb++)
                dd[jb] = dtd[k * 65 + bq + 16 * jb];
#pragma unroll
            for (int ip = 0; ip < 4; ip++)
#pragma unroll
                for (int jb = 0; jb < 4; jb++)
                    fma2p(acc[ip][jb], fd[ip], dd[jb]);
        }
    }

#pragma unroll
    for (int ip = 0; ip < 4; ip++) {
        int sc = sc0 + 2 * (sq + 16 * ip);
#pragma unroll
        for (int jb = 0; jb < 4; jb++) {
            int b = bq + 16 * jb;
            float a0, a1; upk2(acc[ip][jb], a0, a1);
            atomicAdd(&g_z1[sc * B_ + b],       a0);
            atomicAdd(&g_z1[(sc + 1) * B_ + b], a1);
        }
    }
}

// ---------------- K3a: h2[s,:] = silu(embed(v0[s]) @ s_w1 + s_b1) -----------------
__global__ __launch_bounds__(128) void k3a_h2(const float* __restrict__ v0,
                                              const float* __restrict__ s_w1,
                                              const float* __restrict__ s_b1)
{
    __shared__ float e[80];
    int s = blockIdx.x, tid = threadIdx.x;
    if (tid < 80) {
        int d = tid / 10, kk = tid % 10;
        float v = v0[s * 8 + d];
        float f = (float)(1 << (kk % 5));
        e[tid] = (kk < 5) ? __sinf(v * f) : __cosf(v * f);
    }
    __syncthreads();
    float a = s_b1[tid];
#pragma unroll 8
    for (int k = 0; k < 80; k++) a += e[k] * s_w1[k * W_ + tid];
    g_h2[s * W_ + tid] = silu_f(a);
}

// ---------------- KG: g_G[k,cb] += sum over 32 s of h2e[s,k] * silu(z1/N)[s,cb] ---
__global__ __launch_bounds__(256) void kG_contract()
{
    __shared__ float h2s[32 * 129];   // [sl][k], k==128 -> 1 (bias column)
    __shared__ float z1s[32 * 81];    // [sl][cbl]
    int cb0 = blockIdx.x * 80;
    int s0  = blockIdx.y * 32;
    int tid = threadIdx.x;

    for (int i = tid; i < 32 * 32; i += 256) {
        int r = i >> 5, k4 = i & 31;
        float4 v = *(const float4*)&g_h2[(s0 + r) * W_ + 4 * k4];
        h2s[r * 129 + 4 * k4 + 0] = v.x; h2s[r * 129 + 4 * k4 + 1] = v.y;
        h2s[r * 129 + 4 * k4 + 2] = v.z; h2s[r * 129 + 4 * k4 + 3] = v.w;
    }
    if (tid < 32) h2s[tid * 129 + 128] = 1.0f;

    for (int i = tid; i < 32 * 20; i += 256) {
        int r = i / 20, c4 = i - r * 20;
        float4 a = *(const float4*)&g_z1[(s0 + r) * 1280 + cb0 + 4 * c4];
        float* zr = &z1s[r * 81 + 4 * c4];
        zr[0] = silu_f(a.x * (1.0f / (float)NPTS));
        zr[1] = silu_f(a.y * (1.0f / (float)NPTS));
        zr[2] = silu_f(a.z * (1.0f / (float)NPTS));
        zr[3] = silu_f(a.w * (1.0f / (float)NPTS));
    }
    __syncthreads();

    int kq  = tid & 15;   // k = kq + 16*j (j<8), plus k=128 when kq==0
    int cbq = tid >> 4;   // cb = cbq + 16*i (i<5)

    float acc[9][5];
#pragma unroll
    for (int j = 0; j < 9; j++)
#pragma unroll
        for (int i = 0; i < 5; i++) acc[j][i] = 0.0f;

    for (int sl = 0; sl < 32; sl++) {
        float h[9];
#pragma unroll
        for (int j = 0; j < 8; j++) h[j] = h2s[sl * 129 + kq + 16 * j];
        h[8] = h2s[sl * 129 + 128];
        float z[5];
#pragma unroll
        for (int i = 0; i < 5; i++) z[i] = z1s[sl * 81 + cbq + 16 * i];
#pragma unroll
        for (int j = 0; j < 9; j++)
#pragma unroll
            for (int i = 0; i < 5; i++) acc[j][i] += h[j] * z[i];
    }

#pragma unroll
    for (int j = 0; j < 9; j++) {
        int k = kq + 16 * j;
        if (j < 8 || kq == 0) {
#pragma unroll
            for (int i = 0; i < 5; i++)
                atomicAdd(&g_G[k * 1280 + cb0 + cbq + 16 * i], acc[j][i]);
        }
    }
}

// ---------------- KZ: g_z2[b][w] += sum over 30 kc of G[k,cb] * W2ext -------------
__global__ __launch_bounds__(256) void kZ_out(const float* __restrict__ s_w2,
                                              const float* __restrict__ s_b2)
{
    __shared__ float Gt[30 * 64];    // [kcl][b]
    __shared__ float Wt[30 * 128];   // [kcl][w]
    int kc0 = blockIdx.x * 30;
    int tid = threadIdx.x;

    for (int i = tid; i < 30 * 32; i += 256) {
        int kcl = i >> 5, w4 = i & 31;
        int kc = kc0 + kcl, k = kc / 20, c = kc - k * 20;
        float4 v = (k < 128) ? *(const float4*)&s_w2[k * 2560 + c * 128 + 4 * w4]
                             : *(const float4*)&s_b2[c * 128 + 4 * w4];
        *(float4*)&Wt[kcl * 128 + 4 * w4] = v;
    }
    for (int i = tid; i < 30 * 16; i += 256) {
        int kcl = i >> 4, b4 = i & 15;
        int kc = kc0 + kcl, k = kc / 20, c = kc - k * 20;
        float4 a = *(const float4*)&g_G[k * 1280 + c * 64 + 4 * b4];
        *(float4*)&Gt[kcl * 64 + 4 * b4] = a;
    }
    __syncthreads();

    int wq = tid & 15;   // w = wq + 16*m
    int bq = tid >> 4;   // b = bq + 16*i
    float acc[4][8];
#pragma unroll
    for (int i = 0; i < 4; i++)
#pragma unroll
        for (int m = 0; m < 8; m++) acc[i][m] = 0.0f;

    for (int kcl = 0; kcl < 30; kcl++) {
        float g[4];
#pragma unroll
        for (int i = 0; i < 4; i++) g[i] = Gt[kcl * 64 + bq + 16 * i];
#pragma unroll
        for (int m = 0; m < 8; m++) {
            float w = Wt[kcl * 128 + wq + 16 * m];
#pragma unroll
            for (int i = 0; i < 4; i++) acc[i][m] += g[i] * w;
        }
    }
#pragma unroll
    for (int i = 0; i < 4; i++)
#pragma unroll
        for (int m = 0; m < 8; m++)
            atomicAdd(&g_z2[(bq + 16 * i) * W_ + wq + 16 * m], acc[i][m]);
}

// ---------------- K5: residual MLP + pool -----------------------------------------
__global__ __launch_bounds__(128) void k5_head(const float* __restrict__ fc1_w,
                                               const float* __restrict__ fc1_b,
                                               const float* __restrict__ fc2_w,
                                               const float* __restrict__ fc2_b,
                                               const float* __restrict__ pool_w,
                                               const float* __restrict__ pool_b,
                                               float* __restrict__ out)
{
    __shared__ float zs[128], r1[128], r2[128];
    int b = blockIdx.x, w = threadIdx.x;

    float a = g_z2[b * W_ + w] * (1.0f / (float)S_);
    zs[w] = a;
    __syncthreads();

    float u = fc1_b[w];
#pragma unroll 8
    for (int k = 0; k < 128; k++) u += zs[k] * fc1_w[k * W_ + w];
    r1[w] = silu_f(u) + zs[w];
    __syncthreads();

    u = fc2_b[w];
#pragma unroll 8
    for (int k = 0; k < 128; k++) u += r1[k] * fc2_w[k * W_ + w];
    r2[w] = silu_f(u) + r1[w];
    __syncthreads();

    if (w < 10) {
        float o = pool_b[w];
        for (int k = 0; k < 128; k++) o += r2[k] * pool_w[k * 10 + w];
        out[b * 10 + w] = o;
    }
}

// ---------------- host launcher ---------------------------------------------------
extern "C" void kernel_launch(void* const* d_in, const int* in_sizes, int n_in,
                              void* d_out, int out_size)
{
    const float* data   = (const float*)d_in[0];
    const float* v0     = (const float*)d_in[1];
    const float* v_last = (const float*)d_in[2];
    const float* fl_w1  = (const float*)d_in[3];
    const float* fl_b1  = (const float*)d_in[4];
    const float* fl_w2  = (const float*)d_in[5];
    const float* fl_b2  = (const float*)d_in[6];
    const float* fl_w3  = (const float*)d_in[7];
    const float* fl_b3  = (const float*)d_in[8];
    const float* s_w1   = (const float*)d_in[9];
    const float* s_b1   = (const float*)d_in[10];
    const float* s_w2   = (const float*)d_in[11];
    const float* s_b2   = (const float*)d_in[12];
    const float* fc1_w  = (const float*)d_in[13];
    const float* fc1_b  = (const float*)d_in[14];
    const float* fc2_w  = (const float*)d_in[15];
    const float* fc2_b  = (const float*)d_in[16];
    const float* pool_w = (const float*)d_in[17];
    const float* pool_b = (const float*)d_in[18];

    kzero<<<640, 256>>>();
    k3a_h2<<<S_, 128>>>(v0, s_w1, s_b1);
    k1_filt1<<<dim3(7, S_), 128>>>(v_last, fl_w1, fl_b1, fl_w2, fl_b2, fl_w3, fl_b3);
    k2_z1<<<dim3(80, KSPLIT), 256>>>(data);
    kG_contract<<<dim3(16, GSPLIT), 256>>>();
    kZ_out<<<ZSPLIT, 256>>>(s_w2, s_b2);
    k5_head<<<B_, 128>>>(fc1_w, fc1_b, fc2_w, fc2_b, pool_w, pool_b, (float*)d_out);
}